// round 1
// baseline (speedup 1.0000x reference)
#include <cuda_runtime.h>
#include <math.h>

#define NGn   50000
#define NDn   20000
#define HD    128
#define EGGn  800000
#define EGDAn 400000
#define ELABn 200000

// ---------------- scratch (static device allocations; no cudaMalloc) ----------------
__device__ float g_aggA[(size_t)NGn * HD];   // gg aggregation (gene dst)
__device__ float g_aggB[(size_t)NGn * HD];   // reverse gda aggregation (gene dst)
__device__ float g_aggD[(size_t)NDn * HD];   // gda aggregation (disease dst)
__device__ float g_g1[(size_t)NGn * HD];
__device__ float g_d1[(size_t)NDn * HD];
__device__ float g_g2[(size_t)NGn * HD];
__device__ float g_d2[(size_t)NDn * HD];

__device__ float g_W1f[2 * 3 * HD * HD];   // Wd @ Wu_top  per (layer, conv)
__device__ float g_W2f[2 * 3 * HD * HD];   // Ws @ Wu_bot
__device__ float g_bf [2 * 3 * HD];        // fused bias
// final combined weights
__device__ float g_WXg[2 * HD * HD], g_WAg[2 * HD * HD], g_WRg[2 * HD * HD];
__device__ float g_WXd[2 * HD * HD], g_WAd[2 * HD * HD];
__device__ float g_Bg[2 * HD], g_Bd[2 * HD];

__device__ int g_cnt_gg[NGn], g_cnt_rev[NGn], g_cnt_gda[NDn];
__device__ int g_off_gg[NGn], g_off_rev[NGn], g_off_gda[NDn];
__device__ int g_cur_gg[NGn], g_cur_rev[NGn], g_cur_gda[NDn];
__device__ int g_csr_gg[EGGn], g_csr_rev[EGDAn], g_csr_gda[EGDAn];
__device__ int g_bsum[64];
__device__ float g_sum[HD], g_ssq[HD];

// ---------------- selectors for globals (host cannot take device-symbol addresses) ----
__device__ __forceinline__ int*   cnt_of(int e) { return e == 0 ? g_cnt_gg : (e == 1 ? g_cnt_rev : g_cnt_gda); }
__device__ __forceinline__ int*   off_of(int e) { return e == 0 ? g_off_gg : (e == 1 ? g_off_rev : g_off_gda); }
__device__ __forceinline__ int*   cur_of(int e) { return e == 0 ? g_cur_gg : (e == 1 ? g_cur_rev : g_cur_gda); }
__device__ __forceinline__ int*   csr_of(int e) { return e == 0 ? g_csr_gg : (e == 1 ? g_csr_rev : g_csr_gda); }
__device__ __forceinline__ int    ndst_of(int e){ return e == 2 ? NDn : NGn; }
__device__ __forceinline__ float* agg_of(int e) { return e == 0 ? g_aggA : (e == 1 ? g_aggB : g_aggD); }

// ---------------- CSR build --------------------------------------------------------
__global__ void zero_counts_kernel() {
    int i = blockIdx.x * blockDim.x + threadIdx.x;
    if (i < NGn) { g_cnt_gg[i] = 0; g_cnt_rev[i] = 0; }
    if (i < NDn) { g_cnt_gda[i] = 0; }
}

__global__ void hist_kernel(const int* __restrict__ dst, int n, int etype) {
    int* cnt = cnt_of(etype);
    for (int i = blockIdx.x * blockDim.x + threadIdx.x; i < n; i += gridDim.x * blockDim.x)
        atomicAdd(&cnt[dst[i]], 1);
}

// 3-phase exclusive scan over cnt -> off (chunks of 1024 per block, 256 threads)
__global__ void scan_phase1(int n, int etype) {
    const int* cnt = cnt_of(etype);
    int base = blockIdx.x * 1024;
    int s = 0;
    for (int i = threadIdx.x; i < 1024; i += 256) {
        int idx = base + i;
        if (idx < n) s += cnt[idx];
    }
    __shared__ int red[256];
    red[threadIdx.x] = s; __syncthreads();
    for (int d = 128; d > 0; d >>= 1) {
        if (threadIdx.x < d) red[threadIdx.x] += red[threadIdx.x + d];
        __syncthreads();
    }
    if (threadIdx.x == 0) g_bsum[blockIdx.x] = red[0];
}

__global__ void scan_phase2(int nb) {
    if (threadIdx.x == 0 && blockIdx.x == 0) {
        int run = 0;
        for (int b = 0; b < nb; b++) { int t = g_bsum[b]; g_bsum[b] = run; run += t; }
    }
}

__global__ void scan_phase3(int n, int etype) {
    const int* cnt = cnt_of(etype);
    int* off = off_of(etype);
    int* cur = cur_of(etype);
    int base = blockIdx.x * 1024;
    int v[4]; int lsum = 0;
    int i0 = base + threadIdx.x * 4;
    #pragma unroll
    for (int j = 0; j < 4; j++) { v[j] = (i0 + j < n) ? cnt[i0 + j] : 0; lsum += v[j]; }
    __shared__ int ps[256];
    ps[threadIdx.x] = lsum; __syncthreads();
    for (int d = 1; d < 256; d <<= 1) {
        int t = (threadIdx.x >= d) ? ps[threadIdx.x - d] : 0;
        __syncthreads();
        ps[threadIdx.x] += t;
        __syncthreads();
    }
    int run = g_bsum[blockIdx.x] + ps[threadIdx.x] - lsum;
    #pragma unroll
    for (int j = 0; j < 4; j++) {
        if (i0 + j < n) { off[i0 + j] = run; cur[i0 + j] = run; }
        run += v[j];
    }
}

__global__ void fill_kernel(const int* __restrict__ srcv, const int* __restrict__ dsti,
                            int n, int etype) {
    int* cur = cur_of(etype);
    int* csr = csr_of(etype);
    for (int i = blockIdx.x * blockDim.x + threadIdx.x; i < n; i += gridDim.x * blockDim.x) {
        int p = atomicAdd(&cur[dsti[i]], 1);
        csr[p] = srcv[i];
    }
}

// ---------------- fused weight precompute ------------------------------------------
// W1f[l][i] = Wd[l][i] @ Wu[l][i][0:128,:] ; W2f[l][i] = Ws[l][i] @ Wu[l][i][128:256,:]
__global__ void wprod_kernel(const float* __restrict__ Wd1, const float* __restrict__ Ws1,
                             const float* __restrict__ Wu1, const float* __restrict__ Wd2,
                             const float* __restrict__ Ws2, const float* __restrict__ Wu2) {
    int b = blockIdx.x;                  // 48 blocks
    int l = b / 24, i = (b / 8) % 3, rc = b % 8;
    const float* Wd = (l ? Wd2 : Wd1) + i * HD * HD;
    const float* Ws = (l ? Ws2 : Ws1) + i * HD * HD;
    const float* Wu = (l ? Wu2 : Wu1) + i * 2 * HD * HD;
    int h  = threadIdx.x & 127;
    int dg = threadIdx.x >> 7;           // 0/1
    int d0 = rc * 16 + dg * 8;
    float a1[8], a2[8];
    #pragma unroll
    for (int r = 0; r < 8; r++) { a1[r] = 0.f; a2[r] = 0.f; }
    for (int k = 0; k < HD; k++) {
        float wt = Wu[k * HD + h];
        float wb = Wu[(k + HD) * HD + h];
        #pragma unroll
        for (int r = 0; r < 8; r++) {
            a1[r] += Wd[(d0 + r) * HD + k] * wt;
            a2[r] += Ws[(d0 + r) * HD + k] * wb;
        }
    }
    int base = (l * 3 + i) * HD * HD;
    #pragma unroll
    for (int r = 0; r < 8; r++) {
        g_W1f[base + (d0 + r) * HD + h] = a1[r];
        g_W2f[base + (d0 + r) * HD + h] = a2[r];
    }
}

__global__ void wbias_kernel(const float* __restrict__ bd1, const float* __restrict__ bs1,
                             const float* __restrict__ bu1, const float* __restrict__ Wu1,
                             const float* __restrict__ bd2, const float* __restrict__ bs2,
                             const float* __restrict__ bu2, const float* __restrict__ Wu2) {
    int b = blockIdx.x;                  // 6 blocks
    int l = b / 3, i = b % 3;
    const float* bd = (l ? bd2 : bd1) + i * HD;
    const float* bs = (l ? bs2 : bs1) + i * HD;
    const float* bu = (l ? bu2 : bu1) + i * HD;
    const float* Wu = (l ? Wu2 : Wu1) + i * 2 * HD * HD;
    int h = threadIdx.x;
    float acc = bu[h];
    for (int k = 0; k < HD; k++)
        acc += bd[k] * Wu[k * HD + h] + bs[k] * Wu[(k + HD) * HD + h];
    g_bf[(l * 3 + i) * HD + h] = acc;
}

__global__ void wcombine_kernel() {
    int idx = blockIdx.x * blockDim.x + threadIdx.x;   // 2*16384 threads
    if (idx >= 2 * HD * HD) return;
    int l = idx / (HD * HD), e = idx % (HD * HD);
    int base = l * 3 * HD * HD;
    g_WXg[l * HD * HD + e] = 0.5f * (g_W1f[base + e] + g_W1f[base + 2 * HD * HD + e]);
    g_WAg[l * HD * HD + e] = 0.5f * g_W2f[base + e];
    g_WRg[l * HD * HD + e] = 0.5f * g_W2f[base + 2 * HD * HD + e];
    g_WXd[l * HD * HD + e] = g_W1f[base + HD * HD + e];
    g_WAd[l * HD * HD + e] = g_W2f[base + HD * HD + e];
    if (e < HD) {
        g_Bg[l * HD + e] = 0.5f * (g_bf[l * 3 * HD + e] + g_bf[(l * 3 + 2) * HD + e]);
        g_Bd[l * HD + e] = g_bf[(l * 3 + 1) * HD + e];
    }
}

// ---------------- mean aggregation (CSR gather, one warp per dst node) -------------
__global__ void agg_kernel(const float* __restrict__ xext, int xsel, int etype) {
    const float* xsrc = (xsel == 0) ? xext : (xsel == 1 ? g_g1 : g_d1);
    const int* off = off_of(etype);
    const int* cnt = cnt_of(etype);
    const int* csr = csr_of(etype);
    float* agg = agg_of(etype);
    int n_dst = ndst_of(etype);

    int w = (blockIdx.x * blockDim.x + threadIdx.x) >> 5;
    int lane = threadIdx.x & 31;
    if (w >= n_dst) return;
    int o = off[w], c = cnt[w];
    float4 acc = make_float4(0.f, 0.f, 0.f, 0.f);
    for (int j = 0; j < c; j++) {
        int s = csr[o + j];
        float4 v = *(const float4*)(xsrc + (size_t)s * HD + lane * 4);
        acc.x += v.x; acc.y += v.y; acc.z += v.z; acc.w += v.w;
    }
    float sc = 1.0f / fmaxf((float)c, 1.0f);
    acc.x *= sc; acc.y *= sc; acc.z *= sc; acc.w *= sc;
    *(float4*)(agg + (size_t)w * HD + lane * 4) = acc;
}

// ---------------- fused multi-source GEMM: out = bias + sum_s X_s @ W_s ------------
// 64 rows x 128 cols per block, 256 threads, 8x4 per-thread tile.
template <int NSRC>
__global__ void gemm_kernel(const float* __restrict__ Xext, int l) {
    const float *X0, *X1, *X2 = nullptr, *W0, *W1, *W2 = nullptr, *bias;
    float* out; int nrows;
    if (NSRC == 3) {
        X0 = l ? g_g1 : Xext; X1 = g_aggA; X2 = g_aggB;
        W0 = g_WXg + l * HD * HD; W1 = g_WAg + l * HD * HD; W2 = g_WRg + l * HD * HD;
        bias = g_Bg + l * HD; out = l ? g_g2 : g_g1; nrows = NGn;
    } else {
        X0 = l ? g_d1 : Xext; X1 = g_aggD;
        W0 = g_WXd + l * HD * HD; W1 = g_WAd + l * HD * HD;
        bias = g_Bd + l * HD; out = l ? g_d2 : g_d1; nrows = NDn;
    }

    __shared__ float Xs[64][32];
    __shared__ float Ws[32][HD];
    int tid = threadIdx.x;
    int row0 = blockIdx.x * 64;
    int colg = tid & 31;     // 4-col group
    int rowg = tid >> 5;     // 0..7 -> 8 rows each

    float acc[8][4];
    #pragma unroll
    for (int r = 0; r < 8; r++)
        #pragma unroll
        for (int c = 0; c < 4; c++) acc[r][c] = 0.f;

    const float* Xsrc[3] = {X0, X1, X2};
    const float* Wsrc[3] = {W0, W1, W2};

    for (int s = 0; s < NSRC; s++) {
        const float* Xp = Xsrc[s];
        const float* Wp = Wsrc[s];
        for (int kc = 0; kc < 4; kc++) {
            int k0 = kc * 32;
            // stage X tile: 64 rows x 32 k = 512 float4
            #pragma unroll
            for (int i = 0; i < 2; i++) {
                int idx = tid + i * 256;
                int r = idx >> 3;
                int c = (idx & 7) * 4;
                float4 v = make_float4(0.f, 0.f, 0.f, 0.f);
                if (row0 + r < nrows)
                    v = *(const float4*)(Xp + (size_t)(row0 + r) * HD + k0 + c);
                *(float4*)&Xs[r][c] = v;
            }
            // stage W tile: 32 k x 128 h = 1024 float4
            #pragma unroll
            for (int i = 0; i < 4; i++) {
                int idx = tid + i * 256;
                int k = idx >> 5;
                int c = (idx & 31) * 4;
                *(float4*)&Ws[k][c] = *(const float4*)(Wp + (size_t)(k0 + k) * HD + c);
            }
            __syncthreads();
            #pragma unroll
            for (int k = 0; k < 32; k++) {
                float4 wv = *(float4*)&Ws[k][colg * 4];
                #pragma unroll
                for (int r = 0; r < 8; r++) {
                    float xv = Xs[rowg * 8 + r][k];
                    acc[r][0] += xv * wv.x;
                    acc[r][1] += xv * wv.y;
                    acc[r][2] += xv * wv.z;
                    acc[r][3] += xv * wv.w;
                }
            }
            __syncthreads();
        }
    }
    float4 bv = *(const float4*)(bias + colg * 4);
    #pragma unroll
    for (int r = 0; r < 8; r++) {
        int row = row0 + rowg * 8 + r;
        if (row < nrows) {
            float4 o;
            o.x = acc[r][0] + bv.x; o.y = acc[r][1] + bv.y;
            o.z = acc[r][2] + bv.z; o.w = acc[r][3] + bv.w;
            *(float4*)(out + (size_t)row * HD + colg * 4) = o;
        }
    }
}

// ---------------- batchnorm (training-mode stats) + leaky relu ---------------------
__global__ void zero_stats_kernel() {
    g_sum[threadIdx.x] = 0.f; g_ssq[threadIdx.x] = 0.f;
}

__global__ void colstats_kernel(int which) {     // which: 0 = g1 (NG), 1 = d1 (ND)
    const float* x = which ? g_d1 : g_g1;
    int n = which ? NDn : NGn;
    int col = threadIdx.x;
    float s = 0.f, s2 = 0.f;
    for (int r = blockIdx.x; r < n; r += gridDim.x) {
        float v = x[(size_t)r * HD + col];
        s += v; s2 += v * v;
    }
    atomicAdd(&g_sum[col], s);
    atomicAdd(&g_ssq[col], s2);
}

__global__ void bn_apply_kernel(const float* __restrict__ gamma, const float* __restrict__ beta,
                                int which) {
    float* x = which ? g_d1 : g_g1;
    int n = which ? NDn : NGn;
    float inv_n = 1.0f / (float)n;
    size_t total = (size_t)n * HD;
    for (size_t idx = (size_t)blockIdx.x * blockDim.x + threadIdx.x; idx < total;
         idx += (size_t)gridDim.x * blockDim.x) {
        int col = (int)(idx & (HD - 1));
        float m = g_sum[col] * inv_n;
        float v = g_ssq[col] * inv_n - m * m;
        float y = (x[idx] - m) * rsqrtf(v + 1e-5f) * gamma[col] + beta[col];
        x[idx] = (y >= 0.f) ? y : 0.01f * y;
    }
}

// ---------------- decoder: dot(g2[src], d2[dst]) -----------------------------------
__global__ void decoder_kernel(const int* __restrict__ ls, const int* __restrict__ ld,
                               float* __restrict__ out, int n) {
    int e = (blockIdx.x * blockDim.x + threadIdx.x) >> 5;
    int lane = threadIdx.x & 31;
    if (e >= n) return;
    int a = ls[e], b = ld[e];
    float4 u = *(const float4*)(g_g2 + (size_t)a * HD + lane * 4);
    float4 v = *(const float4*)(g_d2 + (size_t)b * HD + lane * 4);
    float p = u.x * v.x + u.y * v.y + u.z * v.z + u.w * v.w;
    #pragma unroll
    for (int off = 16; off > 0; off >>= 1)
        p += __shfl_xor_sync(0xffffffffu, p, off);
    if (lane == 0) out[e] = p;
}

// ---------------- launch -----------------------------------------------------------
extern "C" void kernel_launch(void* const* d_in, const int* in_sizes, int n_in,
                              void* d_out, int out_size) {
    const float* x_gene  = (const float*)d_in[0];
    const float* x_dis   = (const float*)d_in[1];
    const float* W_dst1  = (const float*)d_in[2];
    const float* W_src1  = (const float*)d_in[3];
    const float* W_upd1  = (const float*)d_in[4];
    const float* b_dst1  = (const float*)d_in[5];
    const float* b_src1  = (const float*)d_in[6];
    const float* b_upd1  = (const float*)d_in[7];
    const float* W_dst2  = (const float*)d_in[8];
    const float* W_src2  = (const float*)d_in[9];
    const float* W_upd2  = (const float*)d_in[10];
    const float* b_dst2  = (const float*)d_in[11];
    const float* b_src2  = (const float*)d_in[12];
    const float* b_upd2  = (const float*)d_in[13];
    const float* bn_gamma = (const float*)d_in[14];
    const float* bn_beta  = (const float*)d_in[15];
    const int* gg_src  = (const int*)d_in[16];
    const int* gg_dst  = (const int*)d_in[17];
    const int* gda_src = (const int*)d_in[18];
    const int* gda_dst = (const int*)d_in[19];
    const int* label_src = (const int*)d_in[20];
    const int* label_dst = (const int*)d_in[21];
    float* out = (float*)d_out;

    // --- CSR build (degrees are layout-only; built once per launch) ---
    zero_counts_kernel<<<(NGn + 255) / 256, 256>>>();
    hist_kernel<<<2048, 256>>>(gg_dst,  EGGn,  0);
    hist_kernel<<<2048, 256>>>(gda_src, EGDAn, 1);   // reverse edges: dst = gda_src
    hist_kernel<<<2048, 256>>>(gda_dst, EGDAn, 2);

    int nbG = (NGn + 1023) / 1024, nbD = (NDn + 1023) / 1024;
    scan_phase1<<<nbG, 256>>>(NGn, 0); scan_phase2<<<1, 32>>>(nbG); scan_phase3<<<nbG, 256>>>(NGn, 0);
    scan_phase1<<<nbG, 256>>>(NGn, 1); scan_phase2<<<1, 32>>>(nbG); scan_phase3<<<nbG, 256>>>(NGn, 1);
    scan_phase1<<<nbD, 256>>>(NDn, 2); scan_phase2<<<1, 32>>>(nbD); scan_phase3<<<nbD, 256>>>(NDn, 2);

    fill_kernel<<<2048, 256>>>(gg_src,  gg_dst,  EGGn,  0);
    fill_kernel<<<2048, 256>>>(gda_dst, gda_src, EGDAn, 1);  // values = disease ids, grouped by gene
    fill_kernel<<<2048, 256>>>(gda_src, gda_dst, EGDAn, 2);

    // --- fused weight precompute ---
    wprod_kernel<<<48, 256>>>(W_dst1, W_src1, W_upd1, W_dst2, W_src2, W_upd2);
    wbias_kernel<<<6, HD>>>(b_dst1, b_src1, b_upd1, W_upd1, b_dst2, b_src2, b_upd2, W_upd2);
    wcombine_kernel<<<(2 * HD * HD + 255) / 256, 256>>>();

    const int aggBlkG = (NGn * 32 + 255) / 256;
    const int aggBlkD = (NDn * 32 + 255) / 256;
    const int gemmBlkG = (NGn + 63) / 64;
    const int gemmBlkD = (NDn + 63) / 64;

    for (int l = 0; l < 2; l++) {
        int xg_sel = l ? 1 : 0;   // layer 2 reads g_g1 / g_d1 internally
        int xd_sel = l ? 2 : 0;
        agg_kernel<<<aggBlkG, 256>>>(x_gene, xg_sel, 0);  // gg -> aggA
        agg_kernel<<<aggBlkG, 256>>>(x_dis,  xd_sel, 1);  // rev gda -> aggB
        agg_kernel<<<aggBlkD, 256>>>(x_gene, xg_sel, 2);  // gda -> aggD
        gemm_kernel<3><<<gemmBlkG, 256>>>(x_gene, l);
        gemm_kernel<2><<<gemmBlkD, 256>>>(x_dis,  l);
        if (l == 0) {
            zero_stats_kernel<<<1, HD>>>();
            colstats_kernel<<<512, HD>>>(0);
            bn_apply_kernel<<<4096, 256>>>(bn_gamma,      bn_beta,      0);
            zero_stats_kernel<<<1, HD>>>();
            colstats_kernel<<<512, HD>>>(1);
            bn_apply_kernel<<<4096, 256>>>(bn_gamma + HD, bn_beta + HD, 1);
        }
    }

    decoder_kernel<<<(ELABn * 32 + 255) / 256, 256>>>(label_src, label_dst, out, ELABn);
}

// round 2
// speedup vs baseline: 1.3215x; 1.3215x over previous
#include <cuda_runtime.h>
#include <math.h>
#include <stdint.h>

#define NGn   50000
#define NDn   20000
#define HD    128
#define EGGn  800000
#define EGDAn 400000
#define ELABn 200000

// ---------------- scratch (static device allocations; no cudaMalloc) ----------------
__device__ float g_aggA[(size_t)NGn * HD];   // gg aggregation (gene dst)
__device__ float g_aggB[(size_t)NGn * HD];   // reverse gda aggregation (gene dst)
__device__ float g_aggD[(size_t)NDn * HD];   // gda aggregation (disease dst)
__device__ float g_g1[(size_t)NGn * HD];
__device__ float g_d1[(size_t)NDn * HD];
__device__ float g_g2[(size_t)NGn * HD];
__device__ float g_d2[(size_t)NDn * HD];

__device__ float g_W1f[2 * 3 * HD * HD];   // Wd @ Wu_top  per (layer, conv)
__device__ float g_W2f[2 * 3 * HD * HD];   // Ws @ Wu_bot
__device__ float g_bf [2 * 3 * HD];        // fused bias
// final combined weights
__device__ float g_WXg[2 * HD * HD], g_WAg[2 * HD * HD], g_WRg[2 * HD * HD];
__device__ float g_WXd[2 * HD * HD], g_WAd[2 * HD * HD];
__device__ float g_Bg[2 * HD], g_Bd[2 * HD];

__device__ int g_cnt_gg[NGn], g_cnt_rev[NGn], g_cnt_gda[NDn];
__device__ int g_off_gg[NGn], g_off_rev[NGn], g_off_gda[NDn];
__device__ int g_cur_gg[NGn], g_cur_rev[NGn], g_cur_gda[NDn];
__device__ int g_csr_gg[EGGn], g_csr_rev[EGDAn], g_csr_gda[EGDAn];
__device__ int g_bsum[160];
__device__ float g_sum[2 * HD], g_ssq[2 * HD];

// chunk counts for the combined scan
#define NBG 49                      // ceil(50000/1024)
#define NBD 20                      // ceil(20000/1024)
#define NBTOT (NBG + NBG + NBD)     // 118

// ---------------- selectors ---------------------------------------------------------
__device__ __forceinline__ int*   cnt_of(int e) { return e == 0 ? g_cnt_gg : (e == 1 ? g_cnt_rev : g_cnt_gda); }
__device__ __forceinline__ int*   off_of(int e) { return e == 0 ? g_off_gg : (e == 1 ? g_off_rev : g_off_gda); }
__device__ __forceinline__ int*   cur_of(int e) { return e == 0 ? g_cur_gg : (e == 1 ? g_cur_rev : g_cur_gda); }
__device__ __forceinline__ int*   csr_of(int e) { return e == 0 ? g_csr_gg : (e == 1 ? g_csr_rev : g_csr_gda); }
__device__ __forceinline__ int    ndst_of(int e){ return e == 2 ? NDn : NGn; }

// ---------------- CSR build ---------------------------------------------------------
__global__ void zero_counts_kernel() {
    int i = blockIdx.x * blockDim.x + threadIdx.x;
    if (i < NGn) { g_cnt_gg[i] = 0; g_cnt_rev[i] = 0; }
    if (i < NDn) { g_cnt_gda[i] = 0; }
}

__global__ void hist_all_kernel(const int* __restrict__ gg_dst,
                                const int* __restrict__ gda_src,
                                const int* __restrict__ gda_dst) {
    int total = EGGn + 2 * EGDAn;
    for (int i = blockIdx.x * blockDim.x + threadIdx.x; i < total; i += gridDim.x * blockDim.x) {
        if (i < EGGn) atomicAdd(&g_cnt_gg[gg_dst[i]], 1);
        else if (i < EGGn + EGDAn) atomicAdd(&g_cnt_rev[gda_src[i - EGGn]], 1);
        else atomicAdd(&g_cnt_gda[gda_dst[i - EGGn - EGDAn]], 1);
    }
}

__device__ __forceinline__ void scan_map(int b, int& e, int& chunk) {
    if (b < NBG)            { e = 0; chunk = b; }
    else if (b < 2 * NBG)   { e = 1; chunk = b - NBG; }
    else                    { e = 2; chunk = b - 2 * NBG; }
}

__global__ void scan_phase1() {
    int e, chunk; scan_map(blockIdx.x, e, chunk);
    const int* cnt = cnt_of(e);
    int n = ndst_of(e);
    int base = chunk * 1024;
    int s = 0;
    for (int i = threadIdx.x; i < 1024; i += 256) {
        int idx = base + i;
        if (idx < n) s += cnt[idx];
    }
    __shared__ int red[256];
    red[threadIdx.x] = s; __syncthreads();
    for (int d = 128; d > 0; d >>= 1) {
        if (threadIdx.x < d) red[threadIdx.x] += red[threadIdx.x + d];
        __syncthreads();
    }
    if (threadIdx.x == 0) g_bsum[blockIdx.x] = red[0];
}

__global__ void scan_phase2() {
    if (threadIdx.x == 0 && blockIdx.x == 0) {
        int run = 0;
        for (int b = 0; b < NBG; b++)            { int t = g_bsum[b]; g_bsum[b] = run; run += t; }
        run = 0;
        for (int b = NBG; b < 2 * NBG; b++)      { int t = g_bsum[b]; g_bsum[b] = run; run += t; }
        run = 0;
        for (int b = 2 * NBG; b < NBTOT; b++)    { int t = g_bsum[b]; g_bsum[b] = run; run += t; }
    }
}

__global__ void scan_phase3() {
    int e, chunk; scan_map(blockIdx.x, e, chunk);
    const int* cnt = cnt_of(e);
    int* off = off_of(e);
    int* cur = cur_of(e);
    int n = ndst_of(e);
    int base = chunk * 1024;
    int v[4]; int lsum = 0;
    int i0 = base + threadIdx.x * 4;
    #pragma unroll
    for (int j = 0; j < 4; j++) { v[j] = (i0 + j < n) ? cnt[i0 + j] : 0; lsum += v[j]; }
    __shared__ int ps[256];
    ps[threadIdx.x] = lsum; __syncthreads();
    for (int d = 1; d < 256; d <<= 1) {
        int t = (threadIdx.x >= d) ? ps[threadIdx.x - d] : 0;
        __syncthreads();
        ps[threadIdx.x] += t;
        __syncthreads();
    }
    int run = g_bsum[blockIdx.x] + ps[threadIdx.x] - lsum;
    #pragma unroll
    for (int j = 0; j < 4; j++) {
        if (i0 + j < n) { off[i0 + j] = run; cur[i0 + j] = run; }
        run += v[j];
    }
}

__global__ void fill_all_kernel(const int* __restrict__ gg_src, const int* __restrict__ gg_dst,
                                const int* __restrict__ gda_src, const int* __restrict__ gda_dst) {
    int total = EGGn + 2 * EGDAn;
    for (int i = blockIdx.x * blockDim.x + threadIdx.x; i < total; i += gridDim.x * blockDim.x) {
        if (i < EGGn) {
            int p = atomicAdd(&g_cur_gg[gg_dst[i]], 1);
            g_csr_gg[p] = gg_src[i];
        } else if (i < EGGn + EGDAn) {
            int j = i - EGGn;
            int p = atomicAdd(&g_cur_rev[gda_src[j]], 1);
            g_csr_rev[p] = gda_dst[j];     // values = disease ids, grouped by gene
        } else {
            int j = i - EGGn - EGDAn;
            int p = atomicAdd(&g_cur_gda[gda_dst[j]], 1);
            g_csr_gda[p] = gda_src[j];
        }
    }
}

// ---------------- fused weight precompute -------------------------------------------
__global__ void wprod_kernel(const float* __restrict__ Wd1, const float* __restrict__ Ws1,
                             const float* __restrict__ Wu1, const float* __restrict__ Wd2,
                             const float* __restrict__ Ws2, const float* __restrict__ Wu2) {
    int b = blockIdx.x;                  // 48 blocks
    int l = b / 24, i = (b / 8) % 3, rc = b % 8;
    const float* Wd = (l ? Wd2 : Wd1) + i * HD * HD;
    const float* Ws = (l ? Ws2 : Ws1) + i * HD * HD;
    const float* Wu = (l ? Wu2 : Wu1) + i * 2 * HD * HD;
    int h  = threadIdx.x & 127;
    int dg = threadIdx.x >> 7;           // 0/1
    int d0 = rc * 16 + dg * 8;
    float a1[8], a2[8];
    #pragma unroll
    for (int r = 0; r < 8; r++) { a1[r] = 0.f; a2[r] = 0.f; }
    for (int k = 0; k < HD; k++) {
        float wt = Wu[k * HD + h];
        float wb = Wu[(k + HD) * HD + h];
        #pragma unroll
        for (int r = 0; r < 8; r++) {
            a1[r] += Wd[(d0 + r) * HD + k] * wt;
            a2[r] += Ws[(d0 + r) * HD + k] * wb;
        }
    }
    int base = (l * 3 + i) * HD * HD;
    #pragma unroll
    for (int r = 0; r < 8; r++) {
        g_W1f[base + (d0 + r) * HD + h] = a1[r];
        g_W2f[base + (d0 + r) * HD + h] = a2[r];
    }
}

__global__ void wbias_kernel(const float* __restrict__ bd1, const float* __restrict__ bs1,
                             const float* __restrict__ bu1, const float* __restrict__ Wu1,
                             const float* __restrict__ bd2, const float* __restrict__ bs2,
                             const float* __restrict__ bu2, const float* __restrict__ Wu2) {
    int b = blockIdx.x;                  // 6 blocks
    int l = b / 3, i = b % 3;
    const float* bd = (l ? bd2 : bd1) + i * HD;
    const float* bs = (l ? bs2 : bs1) + i * HD;
    const float* bu = (l ? bu2 : bu1) + i * HD;
    const float* Wu = (l ? Wu2 : Wu1) + i * 2 * HD * HD;
    int h = threadIdx.x;
    float acc = bu[h];
    for (int k = 0; k < HD; k++)
        acc += bd[k] * Wu[k * HD + h] + bs[k] * Wu[(k + HD) * HD + h];
    g_bf[(l * 3 + i) * HD + h] = acc;
}

__global__ void wcombine_kernel() {
    int idx = blockIdx.x * blockDim.x + threadIdx.x;   // 2*16384 threads
    if (idx >= 2 * HD * HD) return;
    int l = idx / (HD * HD), e = idx % (HD * HD);
    int base = l * 3 * HD * HD;
    g_WXg[l * HD * HD + e] = 0.5f * (g_W1f[base + e] + g_W1f[base + 2 * HD * HD + e]);
    g_WAg[l * HD * HD + e] = 0.5f * g_W2f[base + e];
    g_WRg[l * HD * HD + e] = 0.5f * g_W2f[base + 2 * HD * HD + e];
    g_WXd[l * HD * HD + e] = g_W1f[base + HD * HD + e];
    g_WAd[l * HD * HD + e] = g_W2f[base + HD * HD + e];
    if (e < HD) {
        g_Bg[l * HD + e] = 0.5f * (g_bf[l * 3 * HD + e] + g_bf[(l * 3 + 2) * HD + e]);
        g_Bd[l * HD + e] = g_bf[(l * 3 + 1) * HD + e];
    }
}

// ---------------- mean aggregation (CSR gather; all 3 edge types in one launch) -----
__global__ void agg_all_kernel(const float* __restrict__ x_gene,
                               const float* __restrict__ x_dis, int l) {
    int w = (blockIdx.x * blockDim.x + threadIdx.x) >> 5;
    int lane = threadIdx.x & 31;
    int etype, dst;
    if (w < NGn)            { etype = 0; dst = w; }
    else if (w < 2 * NGn)   { etype = 1; dst = w - NGn; }
    else if (w < 2 * NGn + NDn) { etype = 2; dst = w - 2 * NGn; }
    else return;

    const float* xsrc;
    float* agg;
    if (etype == 0)      { xsrc = l ? g_g1 : x_gene; agg = g_aggA; }
    else if (etype == 1) { xsrc = l ? g_d1 : x_dis;  agg = g_aggB; }
    else                 { xsrc = l ? g_g1 : x_gene; agg = g_aggD; }

    const int* off = off_of(etype);
    const int* cnt = cnt_of(etype);
    const int* csr = csr_of(etype);

    int o = off[dst], c = cnt[dst];
    float4 acc = make_float4(0.f, 0.f, 0.f, 0.f);
    for (int j = 0; j < c; j++) {
        int s = csr[o + j];
        float4 v = *(const float4*)(xsrc + (size_t)s * HD + lane * 4);
        acc.x += v.x; acc.y += v.y; acc.z += v.z; acc.w += v.w;
    }
    float sc = 1.0f / fmaxf((float)c, 1.0f);
    acc.x *= sc; acc.y *= sc; acc.z *= sc; acc.w *= sc;
    *(float4*)(agg + (size_t)dst * HD + lane * 4) = acc;
}

// ---------------- tf32 tensor-core GEMM ---------------------------------------------
// out[nrows x 128] = bias + sum_s X_s @ W_s ; block = 128 rows x 128 cols, 8 warps,
// warp tile 32x64 via mma.sync.m16n8k8.tf32. Pitch-36 smem => conflict-free frags.
__device__ __forceinline__ uint32_t f2tf32(float f) {
    uint32_t r;
    asm("cvt.rna.tf32.f32 %0, %1;" : "=r"(r) : "f"(f));
    return r;
}

__device__ __forceinline__ void mma_tf32(float* d, const uint32_t* a, const uint32_t* b) {
    asm volatile(
        "mma.sync.aligned.m16n8k8.row.col.f32.tf32.tf32.f32 "
        "{%0,%1,%2,%3}, {%4,%5,%6,%7}, {%8,%9}, {%0,%1,%2,%3};\n"
        : "+f"(d[0]), "+f"(d[1]), "+f"(d[2]), "+f"(d[3])
        : "r"(a[0]), "r"(a[1]), "r"(a[2]), "r"(a[3]), "r"(b[0]), "r"(b[1]));
}

template <int NSRC>
__global__ __launch_bounds__(256) void gemm_tc_kernel(const float* __restrict__ Xext, int l) {
    const float *X0, *X1, *X2 = nullptr, *W0, *W1, *W2 = nullptr, *bias;
    float* out; int nrows;
    if (NSRC == 3) {
        X0 = l ? g_g1 : Xext; X1 = g_aggA; X2 = g_aggB;
        W0 = g_WXg + l * HD * HD; W1 = g_WAg + l * HD * HD; W2 = g_WRg + l * HD * HD;
        bias = g_Bg + l * HD; out = l ? g_g2 : g_g1; nrows = NGn;
    } else {
        X0 = l ? g_d1 : Xext; X1 = g_aggD;
        W0 = g_WXd + l * HD * HD; W1 = g_WAd + l * HD * HD;
        bias = g_Bd + l * HD; out = l ? g_d2 : g_d1; nrows = NDn;
    }
    const float* Xsrc[3] = {X0, X1, X2};
    const float* Wsrc[3] = {W0, W1, W2};

    __shared__ uint32_t Xs[128][36];   // [row][k], tf32 bits
    __shared__ uint32_t Wst[128][36];  // [n][k] (transposed W chunk), tf32 bits

    int tid = threadIdx.x;
    int warp = tid >> 5, lane = tid & 31;
    int g = lane >> 2, tg = lane & 3;
    int rw = warp >> 1, cw = warp & 1;        // warp tile: rows rw*32, cols cw*64
    int row0 = blockIdx.x * 128;

    float acc[2][8][4];
    #pragma unroll
    for (int mt = 0; mt < 2; mt++)
        #pragma unroll
        for (int nt = 0; nt < 8; nt++)
            #pragma unroll
            for (int i = 0; i < 4; i++) acc[mt][nt][i] = 0.f;

    for (int s = 0; s < NSRC; s++) {
        const float* Xp = Xsrc[s];
        const float* Wp = Wsrc[s];
        for (int kc = 0; kc < 4; kc++) {
            int k0 = kc * 32;
            // stage X: 128 rows x 32 k. 1024 float4-tasks / 256 threads = 4 each.
            #pragma unroll
            for (int i = 0; i < 4; i++) {
                int idx = tid + i * 256;
                int r = idx >> 3;
                int c = (idx & 7) * 4;
                float4 v = make_float4(0.f, 0.f, 0.f, 0.f);
                if (row0 + r < nrows)
                    v = *(const float4*)(Xp + (size_t)(row0 + r) * HD + k0 + c);
                uint4 t;
                t.x = f2tf32(v.x); t.y = f2tf32(v.y); t.z = f2tf32(v.z); t.w = f2tf32(v.w);
                *(uint4*)&Xs[r][c] = t;
            }
            // stage W transposed: tasks = 128 n x 8 k-quads = 1024 / 256 = 4 each.
            // thread loads 4 k-strided scalars (lanes coalesce over n), stores one uint4 row-chunk.
            #pragma unroll
            for (int i = 0; i < 4; i++) {
                int idx = tid + i * 256;
                int n = idx & 127;
                int kq = idx >> 7;            // 0..7
                uint4 t;
                t.x = f2tf32(Wp[(size_t)(k0 + kq * 4 + 0) * HD + n]);
                t.y = f2tf32(Wp[(size_t)(k0 + kq * 4 + 1) * HD + n]);
                t.z = f2tf32(Wp[(size_t)(k0 + kq * 4 + 2) * HD + n]);
                t.w = f2tf32(Wp[(size_t)(k0 + kq * 4 + 3) * HD + n]);
                *(uint4*)&Wst[n][kq * 4] = t;
            }
            __syncthreads();
            #pragma unroll
            for (int k8 = 0; k8 < 4; k8++) {
                int kb = k8 * 8;
                uint32_t a[2][4], b[8][2];
                #pragma unroll
                for (int mt = 0; mt < 2; mt++) {
                    int rb = rw * 32 + mt * 16;
                    a[mt][0] = Xs[rb + g][kb + tg];
                    a[mt][1] = Xs[rb + g + 8][kb + tg];
                    a[mt][2] = Xs[rb + g][kb + tg + 4];
                    a[mt][3] = Xs[rb + g + 8][kb + tg + 4];
                }
                #pragma unroll
                for (int nt = 0; nt < 8; nt++) {
                    int nb = cw * 64 + nt * 8;
                    b[nt][0] = Wst[nb + g][kb + tg];
                    b[nt][1] = Wst[nb + g][kb + tg + 4];
                }
                #pragma unroll
                for (int mt = 0; mt < 2; mt++)
                    #pragma unroll
                    for (int nt = 0; nt < 8; nt++)
                        mma_tf32(acc[mt][nt], a[mt], b[nt]);
            }
            __syncthreads();
        }
    }

    // epilogue: add bias, store float2 (cols 2tg, 2tg+1 are contiguous)
    #pragma unroll
    for (int nt = 0; nt < 8; nt++) {
        int col = cw * 64 + nt * 8 + 2 * tg;
        float2 bv = *(const float2*)(bias + col);
        #pragma unroll
        for (int mt = 0; mt < 2; mt++) {
            int r0 = row0 + rw * 32 + mt * 16 + g;
            if (r0 < nrows) {
                float2 o0 = make_float2(acc[mt][nt][0] + bv.x, acc[mt][nt][1] + bv.y);
                *(float2*)(out + (size_t)r0 * HD + col) = o0;
            }
            int r1 = r0 + 8;
            if (r1 < nrows) {
                float2 o1 = make_float2(acc[mt][nt][2] + bv.x, acc[mt][nt][3] + bv.y);
                *(float2*)(out + (size_t)r1 * HD + col) = o1;
            }
        }
    }
}

// ---------------- batchnorm (training-mode stats) + leaky relu ----------------------
__global__ void zero_stats_kernel() {
    g_sum[threadIdx.x] = 0.f; g_ssq[threadIdx.x] = 0.f;
}

__global__ void colstats_kernel() {   // blocks [0,512): gene; [512,768): disease
    int b = blockIdx.x;
    const float* x; int n, r0, stride, soff;
    if (b < 512) { x = g_g1; n = NGn; r0 = b; stride = 512; soff = 0; }
    else         { x = g_d1; n = NDn; r0 = b - 512; stride = 256; soff = HD; }
    int col = threadIdx.x;
    float s = 0.f, s2 = 0.f;
    for (int r = r0; r < n; r += stride) {
        float v = x[(size_t)r * HD + col];
        s += v; s2 += v * v;
    }
    atomicAdd(&g_sum[soff + col], s);
    atomicAdd(&g_ssq[soff + col], s2);
}

__global__ void bn_apply_kernel(const float* __restrict__ gamma, const float* __restrict__ beta) {
    size_t totalG = (size_t)NGn * HD;
    size_t total = totalG + (size_t)NDn * HD;
    for (size_t idx = (size_t)blockIdx.x * blockDim.x + threadIdx.x; idx < total;
         idx += (size_t)gridDim.x * blockDim.x) {
        float* x; int col; size_t e; float inv_n; int soff;
        if (idx < totalG) { x = g_g1; e = idx; col = (int)(idx & (HD - 1)); inv_n = 1.0f / NGn; soff = 0; }
        else { x = g_d1; e = idx - totalG; col = (int)(e & (HD - 1)); inv_n = 1.0f / NDn; soff = HD; }
        float m = g_sum[soff + col] * inv_n;
        float v = g_ssq[soff + col] * inv_n - m * m;
        float y = (x[e] - m) * rsqrtf(v + 1e-5f) * gamma[soff + col] + beta[soff + col];
        x[e] = (y >= 0.f) ? y : 0.01f * y;
    }
}

// ---------------- decoder: dot(g2[src], d2[dst]) ------------------------------------
__global__ void decoder_kernel(const int* __restrict__ ls, const int* __restrict__ ld,
                               float* __restrict__ out, int n) {
    int e = (blockIdx.x * blockDim.x + threadIdx.x) >> 5;
    int lane = threadIdx.x & 31;
    if (e >= n) return;
    int a = ls[e], b = ld[e];
    float4 u = *(const float4*)(g_g2 + (size_t)a * HD + lane * 4);
    float4 v = *(const float4*)(g_d2 + (size_t)b * HD + lane * 4);
    float p = u.x * v.x + u.y * v.y + u.z * v.z + u.w * v.w;
    #pragma unroll
    for (int off = 16; off > 0; off >>= 1)
        p += __shfl_xor_sync(0xffffffffu, p, off);
    if (lane == 0) out[e] = p;
}

// ---------------- launch ------------------------------------------------------------
extern "C" void kernel_launch(void* const* d_in, const int* in_sizes, int n_in,
                              void* d_out, int out_size) {
    const float* x_gene  = (const float*)d_in[0];
    const float* x_dis   = (const float*)d_in[1];
    const float* W_dst1  = (const float*)d_in[2];
    const float* W_src1  = (const float*)d_in[3];
    const float* W_upd1  = (const float*)d_in[4];
    const float* b_dst1  = (const float*)d_in[5];
    const float* b_src1  = (const float*)d_in[6];
    const float* b_upd1  = (const float*)d_in[7];
    const float* W_dst2  = (const float*)d_in[8];
    const float* W_src2  = (const float*)d_in[9];
    const float* W_upd2  = (const float*)d_in[10];
    const float* b_dst2  = (const float*)d_in[11];
    const float* b_src2  = (const float*)d_in[12];
    const float* b_upd2  = (const float*)d_in[13];
    const float* bn_gamma = (const float*)d_in[14];
    const float* bn_beta  = (const float*)d_in[15];
    const int* gg_src  = (const int*)d_in[16];
    const int* gg_dst  = (const int*)d_in[17];
    const int* gda_src = (const int*)d_in[18];
    const int* gda_dst = (const int*)d_in[19];
    const int* label_src = (const int*)d_in[20];
    const int* label_dst = (const int*)d_in[21];
    float* out = (float*)d_out;

    // --- CSR build ---
    zero_counts_kernel<<<(NGn + 255) / 256, 256>>>();
    hist_all_kernel<<<4096, 256>>>(gg_dst, gda_src, gda_dst);
    scan_phase1<<<NBTOT, 256>>>();
    scan_phase2<<<1, 32>>>();
    scan_phase3<<<NBTOT, 256>>>();
    fill_all_kernel<<<4096, 256>>>(gg_src, gg_dst, gda_src, gda_dst);

    // --- fused weight precompute ---
    wprod_kernel<<<48, 256>>>(W_dst1, W_src1, W_upd1, W_dst2, W_src2, W_upd2);
    wbias_kernel<<<6, HD>>>(b_dst1, b_src1, b_upd1, W_upd1, b_dst2, b_src2, b_upd2, W_upd2);
    wcombine_kernel<<<(2 * HD * HD + 255) / 256, 256>>>();

    const int aggWarps = 2 * NGn + NDn;
    const int aggBlk = (aggWarps * 32 + 255) / 256;
    const int gemmBlkG = (NGn + 127) / 128;
    const int gemmBlkD = (NDn + 127) / 128;

    for (int l = 0; l < 2; l++) {
        agg_all_kernel<<<aggBlk, 256>>>(x_gene, x_dis, l);
        gemm_tc_kernel<3><<<gemmBlkG, 256>>>(x_gene, l);
        gemm_tc_kernel<2><<<gemmBlkD, 256>>>(x_dis,  l);
        if (l == 0) {
            zero_stats_kernel<<<1, 2 * HD>>>();
            colstats_kernel<<<768, HD>>>();
            bn_apply_kernel<<<4096, 256>>>(bn_gamma, bn_beta);
        }
    }

    decoder_kernel<<<(ELABn * 32 + 255) / 256, 256>>>(label_src, label_dst, out, ELABn);
}